// round 1
// baseline (speedup 1.0000x reference)
#include <cuda_runtime.h>
#include <cuda_bf16.h>
#include <math.h>

// Problem constants
#define B_ 2
#define T_ 2048
#define C_ 1024
#define H_ 8
#define D_ 1024
#define V_ 32000
#define HD_ (H_*D_)
#define FF_ (4*C_)

// Scratch (device globals; no dynamic allocation allowed)
__device__ float g_x  [B_*T_*C_];          // residual stream
__device__ float g_h  [B_*T_*C_];          // LN output
__device__ float g_q  [B_*H_*T_*D_];
__device__ float g_k  [B_*H_*T_*D_];
__device__ float g_v  [B_*H_*T_*D_];
__device__ float g_att[B_*T_*HD_];         // attention out, [B,T,H*D] layout
__device__ float g_ffn[B_*T_*FF_];
__device__ float g_wei[(size_t)B_*H_*T_*T_]; // 256 MB score matrix

// ---------------------------------------------------------------------------
// Embedding: x[b,t,c] = tok_emb[idx[b,t],c] + pos_emb[t,c]
// ---------------------------------------------------------------------------
__global__ void embed_kernel(const int* __restrict__ idx,
                             const float* __restrict__ tok,
                             const float* __restrict__ pos) {
    int i = blockIdx.x * blockDim.x + threadIdx.x;   // over B*T*C
    int c  = i % C_;
    int bt = i / C_;
    int t  = bt % T_;
    g_x[i] = tok[(size_t)idx[bt] * C_ + c] + pos[t * C_ + c];
}

// ---------------------------------------------------------------------------
// LayerNorm over last dim (C=1024). One block (256 thr) per row.
// ---------------------------------------------------------------------------
__global__ void ln_kernel(const float* __restrict__ in, float* __restrict__ out,
                          const float* __restrict__ g, const float* __restrict__ b) {
    int row = blockIdx.x;
    const float* x = in + (size_t)row * C_;
    float* o = out + (size_t)row * C_;
    int tid = threadIdx.x;

    __shared__ float rs[256], rss[256];
    float s = 0.f, ss = 0.f;
    for (int c = tid; c < C_; c += 256) { float v = x[c]; s += v; ss += v * v; }
    rs[tid] = s; rss[tid] = ss;
    __syncthreads();
    for (int off = 128; off > 0; off >>= 1) {
        if (tid < off) { rs[tid] += rs[tid + off]; rss[tid] += rss[tid + off]; }
        __syncthreads();
    }
    float mean = rs[0] * (1.0f / C_);
    float var  = rss[0] * (1.0f / C_) - mean * mean;
    float inv  = rsqrtf(var + 1e-5f);
    for (int c = tid; c < C_; c += 256)
        o[c] = (x[c] - mean) * inv * g[c] + b[c];
}

// ---------------------------------------------------------------------------
// SGEMM NN: C[M,N] (+)= scale * A[M,K] @ B[K,N]  (+bias)(+resid)(relu)
// 128x128 tile, BK=8, 256 threads, 8x8 per thread. Batched via blockIdx.z.
// ---------------------------------------------------------------------------
#define BM 128
#define BN 128
#define BK 8
#define TM 8
#define TN 8

#define F_BIAS    1
#define F_ADDC    2
#define F_RELU    4
#define F_CAUSALK 8   // limit K to (blockRow+1)*BM (lower-triangular A in K dim)

__global__ void __launch_bounds__(256)
sgemm_nn(const float* __restrict__ A, const float* __restrict__ Bm,
         float* __restrict__ Cm,
         int M, int N, int K, int lda, int ldb, int ldc,
         long sAb, long sAh, long sBb, long sBh, long sCb, long sCh, int batchH,
         const float* __restrict__ bias, float scale, int flags)
{
    int z  = blockIdx.z;
    int zb = z / batchH, zh = z % batchH;
    A  += zb * sAb + zh * sAh;
    Bm += zb * sBb + zh * sBh;
    Cm += zb * sCb + zh * sCh;

    int bx = blockIdx.x, by = blockIdx.y;
    int row0 = by * BM, col0 = bx * BN;

    int Keff = K;
    if (flags & F_CAUSALK) { int kl = (by + 1) * BM; if (kl < Keff) Keff = kl; }

    __shared__ float As[BK][BM];
    __shared__ float Bs[BK][BN];

    int tid   = threadIdx.x;
    int arow  = tid >> 1, acol4 = (tid & 1) * 4;
    int brow  = tid >> 5, bcol4 = (tid & 31) * 4;

    float acc[TM][TN];
#pragma unroll
    for (int i = 0; i < TM; i++)
#pragma unroll
        for (int j = 0; j < TN; j++) acc[i][j] = 0.f;

    const float* Aptr = A  + (size_t)(row0 + arow) * lda + acol4;
    const float* Bptr = Bm + (size_t)brow * ldb + col0 + bcol4;

    int tr = (tid >> 4) * TM;   // thread row within tile
    int tc = (tid & 15) * TN;   // thread col within tile

    for (int k0 = 0; k0 < Keff; k0 += BK) {
        float4 av = *(const float4*)(Aptr + k0);
        float4 bv = *(const float4*)(Bptr + (size_t)k0 * ldb);
        As[acol4 + 0][arow] = av.x;
        As[acol4 + 1][arow] = av.y;
        As[acol4 + 2][arow] = av.z;
        As[acol4 + 3][arow] = av.w;
        *(float4*)&Bs[brow][bcol4] = bv;
        __syncthreads();
#pragma unroll
        for (int kk = 0; kk < BK; kk++) {
            float ar[TM], br[TN];
#pragma unroll
            for (int i = 0; i < TM; i++) ar[i] = As[kk][tr + i];
#pragma unroll
            for (int j = 0; j < TN; j++) br[j] = Bs[kk][tc + j];
#pragma unroll
            for (int i = 0; i < TM; i++)
#pragma unroll
                for (int j = 0; j < TN; j++) acc[i][j] += ar[i] * br[j];
        }
        __syncthreads();
    }

    int grow = row0 + tr, gcol = col0 + tc;
#pragma unroll
    for (int i = 0; i < TM; i++) {
        size_t roff = (size_t)(grow + i) * ldc + gcol;
#pragma unroll
        for (int j = 0; j < TN; j++) {
            float vv = acc[i][j] * scale;
            if (flags & F_BIAS) vv += bias[gcol + j];
            if (flags & F_RELU) vv = fmaxf(vv, 0.f);
            if (flags & F_ADDC) vv += Cm[roff + j];
            Cm[roff + j] = vv;
        }
    }
}

// ---------------------------------------------------------------------------
// SGEMM NT (scores): C[M,N] = scale * A[M,K] @ B[N,K]^T, causal tile skip.
// A = q[T,D], B = k[T,D], C = wei[T,T]. Skips tiles fully above diagonal.
// ---------------------------------------------------------------------------
__global__ void __launch_bounds__(256)
sgemm_nt_scores(const float* __restrict__ A, const float* __restrict__ Bm,
                float* __restrict__ Cm,
                int M, int N, int K, int lda, int ldb, int ldc,
                long sA, long sB, long sC, float scale)
{
    int bx = blockIdx.x, by = blockIdx.y;
    if (bx > by) return;   // entire tile above diagonal: softmax never reads it

    int z = blockIdx.z;
    A  += (long)z * sA;
    Bm += (long)z * sB;
    Cm += (long)z * sC;

    int row0 = by * BM, col0 = bx * BN;

    __shared__ float As[BK][BM];
    __shared__ float Bs[BK][BN];

    int tid  = threadIdx.x;
    int arow = tid >> 1, acol4 = (tid & 1) * 4;

    float acc[TM][TN];
#pragma unroll
    for (int i = 0; i < TM; i++)
#pragma unroll
        for (int j = 0; j < TN; j++) acc[i][j] = 0.f;

    const float* Aptr = A  + (size_t)(row0 + arow) * lda + acol4;
    const float* Bptr = Bm + (size_t)(col0 + arow) * ldb + acol4;

    int tr = (tid >> 4) * TM;
    int tc = (tid & 15) * TN;

    for (int k0 = 0; k0 < K; k0 += BK) {
        float4 av = *(const float4*)(Aptr + k0);
        float4 bv = *(const float4*)(Bptr + k0);
        As[acol4 + 0][arow] = av.x;
        As[acol4 + 1][arow] = av.y;
        As[acol4 + 2][arow] = av.z;
        As[acol4 + 3][arow] = av.w;
        Bs[acol4 + 0][arow] = bv.x;
        Bs[acol4 + 1][arow] = bv.y;
        Bs[acol4 + 2][arow] = bv.z;
        Bs[acol4 + 3][arow] = bv.w;
        __syncthreads();
#pragma unroll
        for (int kk = 0; kk < BK; kk++) {
            float ar[TM], br[TN];
#pragma unroll
            for (int i = 0; i < TM; i++) ar[i] = As[kk][tr + i];
#pragma unroll
            for (int j = 0; j < TN; j++) br[j] = Bs[kk][tc + j];
#pragma unroll
            for (int i = 0; i < TM; i++)
#pragma unroll
                for (int j = 0; j < TN; j++) acc[i][j] += ar[i] * br[j];
        }
        __syncthreads();
    }

    int grow = row0 + tr, gcol = col0 + tc;
#pragma unroll
    for (int i = 0; i < TM; i++) {
        size_t roff = (size_t)(grow + i) * ldc + gcol;
#pragma unroll
        for (int j = 0; j < TN; j++)
            Cm[roff + j] = acc[i][j] * scale;
    }
}

// ---------------------------------------------------------------------------
// Causal softmax: one block per row (b,h,t). Reads s in [0,t], writes
// normalized probs there, zeros (t, next-128-boundary) so the wei@v GEMM
// (with per-row-block K limit) reads only valid data.
// ---------------------------------------------------------------------------
__global__ void softmax_kernel(float* __restrict__ wei) {
    int row = blockIdx.x;              // bh*T + t
    int t = row % T_;
    float* w = wei + (size_t)row * T_;
    int n = t + 1;
    int tid = threadIdx.x;
    __shared__ float red[256];

    float m = -1e30f;
    for (int s = tid; s < n; s += 256) m = fmaxf(m, w[s]);
    red[tid] = m;
    __syncthreads();
    for (int off = 128; off > 0; off >>= 1) {
        if (tid < off) red[tid] = fmaxf(red[tid], red[tid + off]);
        __syncthreads();
    }
    m = red[0];
    __syncthreads();

    float sum = 0.f;
    for (int s = tid; s < n; s += 256) { float e = expf(w[s] - m); w[s] = e; sum += e; }
    red[tid] = sum;
    __syncthreads();
    for (int off = 128; off > 0; off >>= 1) {
        if (tid < off) red[tid] += red[tid + off];
        __syncthreads();
    }
    float inv = 1.f / red[0];
    for (int s = tid; s < n; s += 256) w[s] *= inv;

    int nend = (n + 127) & ~127;       // zero padding up to 128 boundary
    for (int s = n + tid; s < nend; s += 256) w[s] = 0.f;
}

// ---------------------------------------------------------------------------
// Host launch
// ---------------------------------------------------------------------------
extern "C" void kernel_launch(void* const* d_in, const int* in_sizes, int n_in,
                              void* d_out, int out_size) {
    const int*   idx = (const int*)  d_in[0];
    const float* tok = (const float*)d_in[1];
    const float* pos = (const float*)d_in[2];
    const float* Wq  = (const float*)d_in[3];
    const float* Wk  = (const float*)d_in[4];
    const float* Wv  = (const float*)d_in[5];
    const float* Wo  = (const float*)d_in[6];
    const float* bo  = (const float*)d_in[7];
    const float* W1  = (const float*)d_in[8];
    const float* b1  = (const float*)d_in[9];
    const float* W2  = (const float*)d_in[10];
    const float* b2  = (const float*)d_in[11];
    const float* g1  = (const float*)d_in[12];
    const float* be1 = (const float*)d_in[13];
    const float* g2  = (const float*)d_in[14];
    const float* be2 = (const float*)d_in[15];
    const float* gf  = (const float*)d_in[16];
    const float* bef = (const float*)d_in[17];
    const float* Wlm = (const float*)d_in[18];
    const float* blm = (const float*)d_in[19];
    float* out = (float*)d_out;

    float *x, *h, *q, *k, *v, *att, *ffn, *wei;
    cudaGetSymbolAddress((void**)&x,   g_x);
    cudaGetSymbolAddress((void**)&h,   g_h);
    cudaGetSymbolAddress((void**)&q,   g_q);
    cudaGetSymbolAddress((void**)&k,   g_k);
    cudaGetSymbolAddress((void**)&v,   g_v);
    cudaGetSymbolAddress((void**)&att, g_att);
    cudaGetSymbolAddress((void**)&ffn, g_ffn);
    cudaGetSymbolAddress((void**)&wei, g_wei);

    // 1. embedding
    embed_kernel<<<(B_*T_*C_)/256, 256>>>(idx, tok, pos);

    // 2. LN1
    ln_kernel<<<B_*T_, 256>>>(x, h, g1, be1);

    // 3. q,k,v projections: per (b,h) GEMM [T,C]x[C,D]
    {
        dim3 grid(D_/BN, T_/BM, B_*H_);
        long sAb = (long)T_*C_, sBh = (long)C_*D_;
        long sCb = (long)H_*T_*D_, sCh = (long)T_*D_;
        sgemm_nn<<<grid, 256>>>(h, Wq, q, T_, D_, C_, C_, D_, D_,
                                sAb, 0, 0, sBh, sCb, sCh, H_, nullptr, 1.f, 0);
        sgemm_nn<<<grid, 256>>>(h, Wk, k, T_, D_, C_, C_, D_, D_,
                                sAb, 0, 0, sBh, sCb, sCh, H_, nullptr, 1.f, 0);
        sgemm_nn<<<grid, 256>>>(h, Wv, v, T_, D_, C_, C_, D_, D_,
                                sAb, 0, 0, sBh, sCb, sCh, H_, nullptr, 1.f, 0);
    }

    // 4. scores: wei = q @ k^T * D^-0.5 (causal tile skip)
    {
        dim3 grid(T_/BN, T_/BM, B_*H_);
        sgemm_nt_scores<<<grid, 256>>>(q, k, wei, T_, T_, D_, D_, D_, T_,
                                       (long)T_*D_, (long)T_*D_, (long)T_*T_,
                                       rsqrtf((float)D_));
    }

    // 5. causal softmax
    softmax_kernel<<<B_*H_*T_, 256>>>(wei);

    // 6. att = wei @ v, output directly in [B,T,H*D] layout, K limited per row block
    {
        dim3 grid(D_/BN, T_/BM, B_*H_);
        sgemm_nn<<<grid, 256>>>(wei, v, att, T_, D_, T_, T_, D_, HD_,
                                (long)H_*T_*T_, (long)T_*T_,
                                (long)H_*T_*D_, (long)T_*D_,
                                (long)T_*HD_, (long)D_, H_,
                                nullptr, 1.f, F_CAUSALK);
    }

    // 7. x += att @ Wo + bo
    sgemm_nn<<<dim3(C_/BN, (B_*T_)/BM, 1), 256>>>(
        att, Wo, x, B_*T_, C_, HD_, HD_, C_, C_,
        0, 0, 0, 0, 0, 0, 1, bo, 1.f, F_BIAS | F_ADDC);

    // 8. LN2
    ln_kernel<<<B_*T_, 256>>>(x, h, g2, be2);

    // 9. ffn = relu(h @ W1 + b1)
    sgemm_nn<<<dim3(FF_/BN, (B_*T_)/BM, 1), 256>>>(
        h, W1, ffn, B_*T_, FF_, C_, C_, FF_, FF_,
        0, 0, 0, 0, 0, 0, 1, b1, 1.f, F_BIAS | F_RELU);

    // 10. x += ffn @ W2 + b2
    sgemm_nn<<<dim3(C_/BN, (B_*T_)/BM, 1), 256>>>(
        ffn, W2, x, B_*T_, C_, FF_, FF_, C_, C_,
        0, 0, 0, 0, 0, 0, 1, b2, 1.f, F_BIAS | F_ADDC);

    // 11. final LN
    ln_kernel<<<B_*T_, 256>>>(x, h, gf, bef);

    // 12. logits = h @ Wlm + blm
    sgemm_nn<<<dim3(V_/BN, (B_*T_)/BM, 1), 256>>>(
        h, Wlm, out, B_*T_, V_, C_, C_, V_, V_,
        0, 0, 0, 0, 0, 0, 1, blm, 1.f, F_BIAS);
}

// round 2
// speedup vs baseline: 2.7178x; 2.7178x over previous
#include <cuda_runtime.h>
#include <cuda_bf16.h>
#include <math.h>

// Problem constants
#define B_ 2
#define T_ 2048
#define C_ 1024
#define H_ 8
#define D_ 1024
#define V_ 32000
#define HD_ (H_*D_)
#define FF_ (4*C_)

// Scratch (device globals; no dynamic allocation allowed)
__device__ float g_x  [B_*T_*C_];
__device__ float g_h  [B_*T_*C_];
__device__ float g_q  [B_*H_*T_*D_];
__device__ float g_k  [B_*H_*T_*D_];
__device__ float g_v  [B_*H_*T_*D_];
__device__ float g_att[B_*T_*HD_];
__device__ float g_ffn[B_*T_*FF_];
__device__ float g_wei[(size_t)B_*H_*T_*T_];

#define F_BIAS    1
#define F_ADDC    2
#define F_RELU    4
#define F_CAUSALK 8

// ---------------------------------------------------------------------------
// Embedding
// ---------------------------------------------------------------------------
__global__ void embed_kernel(const int* __restrict__ idx,
                             const float* __restrict__ tok,
                             const float* __restrict__ pos) {
    int i = blockIdx.x * blockDim.x + threadIdx.x;
    int c  = i % C_;
    int bt = i / C_;
    int t  = bt % T_;
    g_x[i] = tok[(size_t)idx[bt] * C_ + c] + pos[t * C_ + c];
}

// ---------------------------------------------------------------------------
// LayerNorm (C=1024), one 256-thread block per row
// ---------------------------------------------------------------------------
__global__ void ln_kernel(const float* __restrict__ in, float* __restrict__ out,
                          const float* __restrict__ g, const float* __restrict__ b) {
    int row = blockIdx.x;
    const float* x = in + (size_t)row * C_;
    float* o = out + (size_t)row * C_;
    int tid = threadIdx.x;

    __shared__ float rs[256], rss[256];
    float s = 0.f, ss = 0.f;
    for (int c = tid; c < C_; c += 256) { float v = x[c]; s += v; ss += v * v; }
    rs[tid] = s; rss[tid] = ss;
    __syncthreads();
    for (int off = 128; off > 0; off >>= 1) {
        if (tid < off) { rs[tid] += rs[tid + off]; rss[tid] += rss[tid + off]; }
        __syncthreads();
    }
    float mean = rs[0] * (1.0f / C_);
    float var  = rss[0] * (1.0f / C_) - mean * mean;
    float inv  = rsqrtf(var + 1e-5f);
    for (int c = tid; c < C_; c += 256)
        o[c] = (x[c] - mean) * inv * g[c] + b[c];
}

// ---------------------------------------------------------------------------
// Causal softmax (zeros padding up to next 128 boundary)
// ---------------------------------------------------------------------------
__global__ void softmax_kernel(float* __restrict__ wei) {
    int row = blockIdx.x;
    int t = row % T_;
    float* w = wei + (size_t)row * T_;
    int n = t + 1;
    int tid = threadIdx.x;
    __shared__ float red[256];

    float m = -1e30f;
    for (int s = tid; s < n; s += 256) m = fmaxf(m, w[s]);
    red[tid] = m;
    __syncthreads();
    for (int off = 128; off > 0; off >>= 1) {
        if (tid < off) red[tid] = fmaxf(red[tid], red[tid + off]);
        __syncthreads();
    }
    m = red[0];
    __syncthreads();

    float sum = 0.f;
    for (int s = tid; s < n; s += 256) { float e = expf(w[s] - m); w[s] = e; sum += e; }
    red[tid] = sum;
    __syncthreads();
    for (int off = 128; off > 0; off >>= 1) {
        if (tid < off) red[tid] += red[tid + off];
        __syncthreads();
    }
    float inv = 1.f / red[0];
    for (int s = tid; s < n; s += 256) w[s] *= inv;

    int nend = (n + 127) & ~127;
    for (int s = n + tid; s < nend; s += 256) w[s] = 0.f;
}

// ---------------------------------------------------------------------------
// tf32 mma helpers
// ---------------------------------------------------------------------------
__device__ __forceinline__ unsigned f2tf(float x) {
    unsigned r;
    asm("cvt.rna.tf32.f32 %0, %1;" : "=r"(r) : "f"(x));
    return r;
}

__device__ __forceinline__ void mma8(float* d, const unsigned* a, unsigned b0, unsigned b1) {
    asm volatile(
        "mma.sync.aligned.m16n8k8.row.col.f32.tf32.tf32.f32 "
        "{%0,%1,%2,%3}, {%4,%5,%6,%7}, {%8,%9}, {%0,%1,%2,%3};\n"
        : "+f"(d[0]), "+f"(d[1]), "+f"(d[2]), "+f"(d[3])
        : "r"(a[0]), "r"(a[1]), "r"(a[2]), "r"(a[3]), "r"(b0), "r"(b1));
}

#define PADW 136   // smem row stride in floats; 136 % 32 == 8 -> conflict-free frags

// Fragment compute for one k8 slice: 32 mmas per warp (4 m-tiles x 8 n-tiles)
__device__ __forceinline__ void compute_k8(
    const float (* __restrict__ As)[PADW], const float (* __restrict__ Bs)[PADW],
    float acc[4][8][4], int kk, int wm, int wn, int g, int tig)
{
    unsigned a[4][4];
#pragma unroll
    for (int mt = 0; mt < 4; mt++) {
        int mrow = wm * 64 + mt * 16;
        a[mt][0] = f2tf(As[kk + tig    ][mrow + g    ]);
        a[mt][1] = f2tf(As[kk + tig    ][mrow + g + 8]);
        a[mt][2] = f2tf(As[kk + tig + 4][mrow + g    ]);
        a[mt][3] = f2tf(As[kk + tig + 4][mrow + g + 8]);
    }
#pragma unroll
    for (int nt = 0; nt < 8; nt++) {
        int ncol = wn * 64 + nt * 8 + g;
        unsigned b0 = f2tf(Bs[kk + tig    ][ncol]);
        unsigned b1 = f2tf(Bs[kk + tig + 4][ncol]);
#pragma unroll
        for (int mt = 0; mt < 4; mt++) mma8(acc[mt][nt], a[mt], b0, b1);
    }
}

// ---------------------------------------------------------------------------
// tf32 GEMM NN: C[M,N] (+)= scale*A[M,K]@B[K,N] (+bias)(+resid)(relu)(causalK)
// 128x128 tile, BK=16, 128 threads (4 warps of 64x64), double-buffered smem.
// ---------------------------------------------------------------------------
__global__ void __launch_bounds__(128)
mma_nn(const float* __restrict__ A, const float* __restrict__ Bm,
       float* __restrict__ Cm,
       int M, int N, int K, int lda, int ldb, int ldc,
       long sAb, long sAh, long sBb, long sBh, long sCb, long sCh, int batchH,
       const float* __restrict__ bias, float scale, int flags)
{
    __shared__ float As[2][16][PADW];
    __shared__ float Bs[2][16][PADW];

    int z  = blockIdx.z;
    int zb = z / batchH, zh = z % batchH;
    A  += zb * sAb + zh * sAh;
    Bm += zb * sBb + zh * sBh;
    Cm += zb * sCb + zh * sCh;

    int bx = blockIdx.x, by = blockIdx.y;
    int row0 = by * 128, col0 = bx * 128;

    int Keff = K;
    if (flags & F_CAUSALK) { int kl = (by + 1) * 128; if (kl < Keff) Keff = kl; }

    int tid  = threadIdx.x;
    int lane = tid & 31, warp = tid >> 5;
    int wm = warp >> 1, wn = warp & 1;
    int g  = lane >> 2, tig = lane & 3;

    const float* Ap = A  + (size_t)(row0 + tid) * lda;                 // thread owns one A row
    const float* Bp = Bm + (size_t)(tid >> 5) * ldb + col0 + lane * 4; // 4 k-rows per pass

    float acc[4][8][4];
#pragma unroll
    for (int i = 0; i < 4; i++)
#pragma unroll
        for (int j = 0; j < 8; j++)
#pragma unroll
            for (int r = 0; r < 4; r++) acc[i][j][r] = 0.f;

    float4 Ar[4], Br[4];
    // prologue: k0 = 0
#pragma unroll
    for (int i = 0; i < 4; i++) Ar[i] = *(const float4*)(Ap + 4 * i);
#pragma unroll
    for (int i = 0; i < 4; i++) Br[i] = *(const float4*)(Bp + (size_t)(4 * i) * ldb);
#pragma unroll
    for (int i = 0; i < 4; i++) {
        As[0][4*i+0][tid] = Ar[i].x; As[0][4*i+1][tid] = Ar[i].y;
        As[0][4*i+2][tid] = Ar[i].z; As[0][4*i+3][tid] = Ar[i].w;
    }
#pragma unroll
    for (int i = 0; i < 4; i++)
        *(float4*)&Bs[0][(tid >> 5) + 4 * i][lane * 4] = Br[i];
    __syncthreads();

    int cur = 0;
    int iters = Keff / 16;
    for (int it = 0; it < iters; ++it) {
        bool hasNext = (it + 1 < iters);
        if (hasNext) {
            int k0 = (it + 1) * 16;
#pragma unroll
            for (int i = 0; i < 4; i++) Ar[i] = *(const float4*)(Ap + k0 + 4 * i);
#pragma unroll
            for (int i = 0; i < 4; i++) Br[i] = *(const float4*)(Bp + (size_t)(k0 + 4 * i) * ldb);
        }
        compute_k8(As[cur], Bs[cur], acc, 0, wm, wn, g, tig);
        compute_k8(As[cur], Bs[cur], acc, 8, wm, wn, g, tig);
        if (hasNext) {
            int nxt = cur ^ 1;
#pragma unroll
            for (int i = 0; i < 4; i++) {
                As[nxt][4*i+0][tid] = Ar[i].x; As[nxt][4*i+1][tid] = Ar[i].y;
                As[nxt][4*i+2][tid] = Ar[i].z; As[nxt][4*i+3][tid] = Ar[i].w;
            }
#pragma unroll
            for (int i = 0; i < 4; i++)
                *(float4*)&Bs[nxt][(tid >> 5) + 4 * i][lane * 4] = Br[i];
            __syncthreads();
            cur = nxt;
        }
    }

    // epilogue
#pragma unroll
    for (int mt = 0; mt < 4; mt++) {
#pragma unroll
        for (int nt = 0; nt < 8; nt++) {
            int r = row0 + wm * 64 + mt * 16 + g;
            int c = col0 + wn * 64 + nt * 8 + tig * 2;
#pragma unroll
            for (int half = 0; half < 2; half++) {
                float* p = Cm + (size_t)(r + 8 * half) * ldc + c;
                float x0 = acc[mt][nt][2*half + 0] * scale;
                float x1 = acc[mt][nt][2*half + 1] * scale;
                if (flags & F_BIAS) { x0 += bias[c]; x1 += bias[c + 1]; }
                if (flags & F_RELU) { x0 = fmaxf(x0, 0.f); x1 = fmaxf(x1, 0.f); }
                if (flags & F_ADDC) { x0 += p[0]; x1 += p[1]; }
                p[0] = x0; p[1] = x1;
            }
        }
    }
}

// ---------------------------------------------------------------------------
// tf32 GEMM NT (scores): C[M,N] = scale * A[M,K] @ B[N,K]^T, causal tile skip
// ---------------------------------------------------------------------------
__global__ void __launch_bounds__(128)
mma_nt_scores(const float* __restrict__ A, const float* __restrict__ Bm,
              float* __restrict__ Cm,
              int K, int lda, int ldb, int ldc,
              long sA, long sB, long sC, float scale)
{
    int bx = blockIdx.x, by = blockIdx.y;
    if (bx > by) return;

    __shared__ float As[2][16][PADW];
    __shared__ float Bs[2][16][PADW];

    int z = blockIdx.z;
    A  += (long)z * sA;
    Bm += (long)z * sB;
    Cm += (long)z * sC;

    int row0 = by * 128, col0 = bx * 128;

    int tid  = threadIdx.x;
    int lane = tid & 31, warp = tid >> 5;
    int wm = warp >> 1, wn = warp & 1;
    int g  = lane >> 2, tig = lane & 3;

    const float* Ap = A  + (size_t)(row0 + tid) * lda;
    const float* Bp = Bm + (size_t)(col0 + tid) * ldb;   // row of k-matrix = col of B^T

    float acc[4][8][4];
#pragma unroll
    for (int i = 0; i < 4; i++)
#pragma unroll
        for (int j = 0; j < 8; j++)
#pragma unroll
            for (int r = 0; r < 4; r++) acc[i][j][r] = 0.f;

    float4 Ar[4], Br[4];
#pragma unroll
    for (int i = 0; i < 4; i++) Ar[i] = *(const float4*)(Ap + 4 * i);
#pragma unroll
    for (int i = 0; i < 4; i++) Br[i] = *(const float4*)(Bp + 4 * i);
#pragma unroll
    for (int i = 0; i < 4; i++) {
        As[0][4*i+0][tid] = Ar[i].x; As[0][4*i+1][tid] = Ar[i].y;
        As[0][4*i+2][tid] = Ar[i].z; As[0][4*i+3][tid] = Ar[i].w;
        Bs[0][4*i+0][tid] = Br[i].x; Bs[0][4*i+1][tid] = Br[i].y;
        Bs[0][4*i+2][tid] = Br[i].z; Bs[0][4*i+3][tid] = Br[i].w;
    }
    __syncthreads();

    int cur = 0;
    int iters = K / 16;
    for (int it = 0; it < iters; ++it) {
        bool hasNext = (it + 1 < iters);
        if (hasNext) {
            int k0 = (it + 1) * 16;
#pragma unroll
            for (int i = 0; i < 4; i++) Ar[i] = *(const float4*)(Ap + k0 + 4 * i);
#pragma unroll
            for (int i = 0; i < 4; i++) Br[i] = *(const float4*)(Bp + k0 + 4 * i);
        }
        compute_k8(As[cur], Bs[cur], acc, 0, wm, wn, g, tig);
        compute_k8(As[cur], Bs[cur], acc, 8, wm, wn, g, tig);
        if (hasNext) {
            int nxt = cur ^ 1;
#pragma unroll
            for (int i = 0; i < 4; i++) {
                As[nxt][4*i+0][tid] = Ar[i].x; As[nxt][4*i+1][tid] = Ar[i].y;
                As[nxt][4*i+2][tid] = Ar[i].z; As[nxt][4*i+3][tid] = Ar[i].w;
                Bs[nxt][4*i+0][tid] = Br[i].x; Bs[nxt][4*i+1][tid] = Br[i].y;
                Bs[nxt][4*i+2][tid] = Br[i].z; Bs[nxt][4*i+3][tid] = Br[i].w;
            }
            __syncthreads();
            cur = nxt;
        }
    }

#pragma unroll
    for (int mt = 0; mt < 4; mt++) {
#pragma unroll
        for (int nt = 0; nt < 8; nt++) {
            int r = row0 + wm * 64 + mt * 16 + g;
            int c = col0 + wn * 64 + nt * 8 + tig * 2;
#pragma unroll
            for (int half = 0; half < 2; half++) {
                float* p = Cm + (size_t)(r + 8 * half) * ldc + c;
                p[0] = acc[mt][nt][2*half + 0] * scale;
                p[1] = acc[mt][nt][2*half + 1] * scale;
            }
        }
    }
}

// ---------------------------------------------------------------------------
// Host launch
// ---------------------------------------------------------------------------
extern "C" void kernel_launch(void* const* d_in, const int* in_sizes, int n_in,
                              void* d_out, int out_size) {
    const int*   idx = (const int*)  d_in[0];
    const float* tok = (const float*)d_in[1];
    const float* pos = (const float*)d_in[2];
    const float* Wq  = (const float*)d_in[3];
    const float* Wk  = (const float*)d_in[4];
    const float* Wv  = (const float*)d_in[5];
    const float* Wo  = (const float*)d_in[6];
    const float* bo  = (const float*)d_in[7];
    const float* W1  = (const float*)d_in[8];
    const float* b1  = (const float*)d_in[9];
    const float* W2  = (const float*)d_in[10];
    const float* b2  = (const float*)d_in[11];
    const float* g1  = (const float*)d_in[12];
    const float* be1 = (const float*)d_in[13];
    const float* g2  = (const float*)d_in[14];
    const float* be2 = (const float*)d_in[15];
    const float* gf  = (const float*)d_in[16];
    const float* bef = (const float*)d_in[17];
    const float* Wlm = (const float*)d_in[18];
    const float* blm = (const float*)d_in[19];
    float* out = (float*)d_out;

    float *x, *h, *q, *k, *v, *att, *ffn, *wei;
    cudaGetSymbolAddress((void**)&x,   g_x);
    cudaGetSymbolAddress((void**)&h,   g_h);
    cudaGetSymbolAddress((void**)&q,   g_q);
    cudaGetSymbolAddress((void**)&k,   g_k);
    cudaGetSymbolAddress((void**)&v,   g_v);
    cudaGetSymbolAddress((void**)&att, g_att);
    cudaGetSymbolAddress((void**)&ffn, g_ffn);
    cudaGetSymbolAddress((void**)&wei, g_wei);

    // 1. embedding
    embed_kernel<<<(B_*T_*C_)/256, 256>>>(idx, tok, pos);

    // 2. LN1
    ln_kernel<<<B_*T_, 256>>>(x, h, g1, be1);

    // 3. q,k,v projections
    {
        dim3 grid(D_/128, T_/128, B_*H_);
        long sAb = (long)T_*C_, sBh = (long)C_*D_;
        long sCb = (long)H_*T_*D_, sCh = (long)T_*D_;
        mma_nn<<<grid, 128>>>(h, Wq, q, T_, D_, C_, C_, D_, D_,
                              sAb, 0, 0, sBh, sCb, sCh, H_, nullptr, 1.f, 0);
        mma_nn<<<grid, 128>>>(h, Wk, k, T_, D_, C_, C_, D_, D_,
                              sAb, 0, 0, sBh, sCb, sCh, H_, nullptr, 1.f, 0);
        mma_nn<<<grid, 128>>>(h, Wv, v, T_, D_, C_, C_, D_, D_,
                              sAb, 0, 0, sBh, sCb, sCh, H_, nullptr, 1.f, 0);
    }

    // 4. scores
    {
        dim3 grid(T_/128, T_/128, B_*H_);
        mma_nt_scores<<<grid, 128>>>(q, k, wei, D_, D_, D_, T_,
                                     (long)T_*D_, (long)T_*D_, (long)T_*T_,
                                     rsqrtf((float)D_));
    }

    // 5. softmax
    softmax_kernel<<<B_*H_*T_, 256>>>(wei);

    // 6. att = wei @ v  ([B,T,H*D] layout, causal K-limit)
    {
        dim3 grid(D_/128, T_/128, B_*H_);
        mma_nn<<<grid, 128>>>(wei, v, att, T_, D_, T_, T_, D_, HD_,
                              (long)H_*T_*T_, (long)T_*T_,
                              (long)H_*T_*D_, (long)T_*D_,
                              (long)T_*HD_, (long)D_, H_,
                              nullptr, 1.f, F_CAUSALK);
    }

    // 7. x += att @ Wo + bo
    mma_nn<<<dim3(C_/128, (B_*T_)/128, 1), 128>>>(
        att, Wo, x, B_*T_, C_, HD_, HD_, C_, C_,
        0, 0, 0, 0, 0, 0, 1, bo, 1.f, F_BIAS | F_ADDC);

    // 8. LN2
    ln_kernel<<<B_*T_, 256>>>(x, h, g2, be2);

    // 9. ffn = relu(h @ W1 + b1)
    mma_nn<<<dim3(FF_/128, (B_*T_)/128, 1), 128>>>(
        h, W1, ffn, B_*T_, FF_, C_, C_, FF_, FF_,
        0, 0, 0, 0, 0, 0, 1, b1, 1.f, F_BIAS | F_RELU);

    // 10. x += ffn @ W2 + b2
    mma_nn<<<dim3(C_/128, (B_*T_)/128, 1), 128>>>(
        ffn, W2, x, B_*T_, C_, FF_, FF_, C_, C_,
        0, 0, 0, 0, 0, 0, 1, b2, 1.f, F_BIAS | F_ADDC);

    // 11. final LN
    ln_kernel<<<B_*T_, 256>>>(x, h, gf, bef);

    // 12. logits = h @ Wlm + blm
    mma_nn<<<dim3(V_/128, (B_*T_)/128, 1), 128>>>(
        h, Wlm, out, B_*T_, V_, C_, C_, V_, V_,
        0, 0, 0, 0, 0, 0, 1, blm, 1.f, F_BIAS);
}

// round 3
// speedup vs baseline: 3.6392x; 1.3390x over previous
#include <cuda_runtime.h>
#include <cuda_bf16.h>
#include <math.h>

// Problem constants
#define B_ 2
#define T_ 2048
#define C_ 1024
#define H_ 8
#define D_ 1024
#define V_ 32000
#define HD_ (H_*D_)
#define FF_ (4*C_)

// Scratch (device globals; no dynamic allocation allowed)
__device__ float g_x  [B_*T_*C_];
__device__ float g_h  [B_*T_*C_];
__device__ float g_q  [B_*H_*T_*D_];
__device__ float g_k  [B_*H_*T_*D_];
__device__ float g_v  [B_*H_*T_*D_];
__device__ float g_att[B_*T_*HD_];
__device__ float g_ffn[B_*T_*FF_];
__device__ float g_wei[(size_t)B_*H_*T_*T_];

#define F_BIAS    1
#define F_ADDC    2
#define F_RELU    4
#define F_CAUSALK 8

// ---------------------------------------------------------------------------
// Embedding
// ---------------------------------------------------------------------------
__global__ void embed_kernel(const int* __restrict__ idx,
                             const float* __restrict__ tok,
                             const float* __restrict__ pos) {
    int i = blockIdx.x * blockDim.x + threadIdx.x;
    int c  = i % C_;
    int bt = i / C_;
    int t  = bt % T_;
    g_x[i] = tok[(size_t)idx[bt] * C_ + c] + pos[t * C_ + c];
}

// ---------------------------------------------------------------------------
// LayerNorm (C=1024), one 256-thread block per row
// ---------------------------------------------------------------------------
__global__ void ln_kernel(const float* __restrict__ in, float* __restrict__ out,
                          const float* __restrict__ g, const float* __restrict__ b) {
    int row = blockIdx.x;
    const float* x = in + (size_t)row * C_;
    float* o = out + (size_t)row * C_;
    int tid = threadIdx.x;

    __shared__ float rs[256], rss[256];
    float s = 0.f, ss = 0.f;
    for (int c = tid; c < C_; c += 256) { float v = x[c]; s += v; ss += v * v; }
    rs[tid] = s; rss[tid] = ss;
    __syncthreads();
    for (int off = 128; off > 0; off >>= 1) {
        if (tid < off) { rs[tid] += rs[tid + off]; rss[tid] += rss[tid + off]; }
        __syncthreads();
    }
    float mean = rs[0] * (1.0f / C_);
    float var  = rss[0] * (1.0f / C_) - mean * mean;
    float inv  = rsqrtf(var + 1e-5f);
    for (int c = tid; c < C_; c += 256)
        o[c] = (x[c] - mean) * inv * g[c] + b[c];
}

// ---------------------------------------------------------------------------
// Causal softmax (zeros padding up to next 128 boundary)
// ---------------------------------------------------------------------------
__global__ void softmax_kernel(float* __restrict__ wei) {
    int row = blockIdx.x;
    int t = row % T_;
    float* w = wei + (size_t)row * T_;
    int n = t + 1;
    int tid = threadIdx.x;
    __shared__ float red[256];

    float m = -1e30f;
    for (int s = tid; s < n; s += 256) m = fmaxf(m, w[s]);
    red[tid] = m;
    __syncthreads();
    for (int off = 128; off > 0; off >>= 1) {
        if (tid < off) red[tid] = fmaxf(red[tid], red[tid + off]);
        __syncthreads();
    }
    m = red[0];
    __syncthreads();

    float sum = 0.f;
    for (int s = tid; s < n; s += 256) { float e = expf(w[s] - m); w[s] = e; sum += e; }
    red[tid] = sum;
    __syncthreads();
    for (int off = 128; off > 0; off >>= 1) {
        if (tid < off) red[tid] += red[tid + off];
        __syncthreads();
    }
    float inv = 1.f / red[0];
    for (int s = tid; s < n; s += 256) w[s] *= inv;

    int nend = (n + 127) & ~127;
    for (int s = n + tid; s < nend; s += 256) w[s] = 0.f;
}

// ---------------------------------------------------------------------------
// tf32 mma helpers
// ---------------------------------------------------------------------------
__device__ __forceinline__ unsigned f2tf(float x) {
    unsigned r;
    asm("cvt.rna.tf32.f32 %0, %1;" : "=r"(r) : "f"(x));
    return r;
}

__device__ __forceinline__ void mma8(float* d, const unsigned* a, unsigned b0, unsigned b1) {
    asm volatile(
        "mma.sync.aligned.m16n8k8.row.col.f32.tf32.tf32.f32 "
        "{%0,%1,%2,%3}, {%4,%5,%6,%7}, {%8,%9}, {%0,%1,%2,%3};\n"
        : "+f"(d[0]), "+f"(d[1]), "+f"(d[2]), "+f"(d[3])
        : "r"(a[0]), "r"(a[1]), "r"(a[2]), "r"(a[3]), "r"(b0), "r"(b1));
}

__device__ __forceinline__ void cp16(void* s, const void* g) {
    unsigned sa = (unsigned)__cvta_generic_to_shared(s);
    asm volatile("cp.async.cg.shared.global [%0], [%1], 16;\n" :: "r"(sa), "l"(g));
}
__device__ __forceinline__ void cp_commit() {
    asm volatile("cp.async.commit_group;\n" ::);
}

// A-style tile: [128 rows][k, stride 20]  (banks 20g+tig -> conflict-free)
// B-style tile: [16 k-rows][col, stride 136] (banks 8tig+g -> conflict-free)
#define AP 20
#define BP 136

// Fragment compute, A-style operand As[m][k], B-style operand Bs[k][n]
__device__ __forceinline__ void compute_k8_nn(
    const float (* __restrict__ As)[AP], const float (* __restrict__ Bs)[BP],
    float acc[4][8][4], int kk, int wm, int wn, int g, int tig)
{
    unsigned a[4][4];
#pragma unroll
    for (int mt = 0; mt < 4; mt++) {
        int mrow = wm * 64 + mt * 16;
        a[mt][0] = f2tf(As[mrow + g    ][kk + tig    ]);
        a[mt][1] = f2tf(As[mrow + g + 8][kk + tig    ]);
        a[mt][2] = f2tf(As[mrow + g    ][kk + tig + 4]);
        a[mt][3] = f2tf(As[mrow + g + 8][kk + tig + 4]);
    }
#pragma unroll
    for (int nt = 0; nt < 8; nt++) {
        int ncol = wn * 64 + nt * 8 + g;
        unsigned b0 = f2tf(Bs[kk + tig    ][ncol]);
        unsigned b1 = f2tf(Bs[kk + tig + 4][ncol]);
#pragma unroll
        for (int mt = 0; mt < 4; mt++) mma8(acc[mt][nt], a[mt], b0, b1);
    }
}

// Fragment compute, both operands A-style (NT: B[n][k])
__device__ __forceinline__ void compute_k8_nt(
    const float (* __restrict__ As)[AP], const float (* __restrict__ Bt)[AP],
    float acc[4][8][4], int kk, int wm, int wn, int g, int tig)
{
    unsigned a[4][4];
#pragma unroll
    for (int mt = 0; mt < 4; mt++) {
        int mrow = wm * 64 + mt * 16;
        a[mt][0] = f2tf(As[mrow + g    ][kk + tig    ]);
        a[mt][1] = f2tf(As[mrow + g + 8][kk + tig    ]);
        a[mt][2] = f2tf(As[mrow + g    ][kk + tig + 4]);
        a[mt][3] = f2tf(As[mrow + g + 8][kk + tig + 4]);
    }
#pragma unroll
    for (int nt = 0; nt < 8; nt++) {
        int ncol = wn * 64 + nt * 8 + g;
        unsigned b0 = f2tf(Bt[ncol][kk + tig    ]);
        unsigned b1 = f2tf(Bt[ncol][kk + tig + 4]);
#pragma unroll
        for (int mt = 0; mt < 4; mt++) mma8(acc[mt][nt], a[mt], b0, b1);
    }
}

// ---------------------------------------------------------------------------
// tf32 GEMM NN: C[M,N] (+)= scale*A[M,K]@B[K,N] (+bias)(+resid)(relu)(causalK)
// 128x128 tile, BK=16, 128 threads, cp.async double-buffered.
// ---------------------------------------------------------------------------
__global__ void __launch_bounds__(128, 3)
mma_nn(const float* __restrict__ A, const float* __restrict__ Bm,
       float* __restrict__ Cm,
       int K, int lda, int ldb, int ldc,
       long sAb, long sAh, long sBb, long sBh, long sCb, long sCh, int batchH,
       const float* __restrict__ bias, float scale, int flags)
{
    __shared__ float As[2][128][AP];
    __shared__ float Bs[2][16][BP];

    int z  = blockIdx.z;
    int zb = z / batchH, zh = z % batchH;
    A  += zb * sAb + zh * sAh;
    Bm += zb * sBb + zh * sBh;
    Cm += zb * sCb + zh * sCh;

    int bx = blockIdx.x, by = blockIdx.y;
    int row0 = by * 128, col0 = bx * 128;

    int Keff = K;
    if (flags & F_CAUSALK) { int kl = (by + 1) * 128; if (kl < Keff) Keff = kl; }

    int tid  = threadIdx.x;
    int lane = tid & 31, warp = tid >> 5;
    int wm = warp >> 1, wn = warp & 1;
    int g  = lane >> 2, tig = lane & 3;

    const float* Ag = A  + (size_t)row0 * lda;
    const float* Bg = Bm + col0;
    int arow = tid >> 2, ac = (tid & 3) * 4;   // A: 32 rows x 16k per pass
    int brow = tid >> 5, bc = (tid & 31) * 4;  // B: 4 k-rows x 128 cols per pass

    float acc[4][8][4];
#pragma unroll
    for (int i = 0; i < 4; i++)
#pragma unroll
        for (int j = 0; j < 8; j++)
#pragma unroll
            for (int r = 0; r < 4; r++) acc[i][j][r] = 0.f;

    int iters = Keff / 16;

    // prologue: stage 0
    {
#pragma unroll
        for (int p = 0; p < 4; p++)
            cp16(&As[0][arow + 32 * p][ac], Ag + (size_t)(arow + 32 * p) * lda + ac);
#pragma unroll
        for (int p = 0; p < 4; p++)
            cp16(&Bs[0][brow + 4 * p][bc], Bg + (size_t)(brow + 4 * p) * ldb + bc);
        cp_commit();
    }

    int cur = 0;
    for (int it = 0; it < iters; ++it) {
        bool hn = (it + 1 < iters);
        if (hn) {
            int k0 = (it + 1) * 16;
            int nxt = cur ^ 1;
#pragma unroll
            for (int p = 0; p < 4; p++)
                cp16(&As[nxt][arow + 32 * p][ac], Ag + (size_t)(arow + 32 * p) * lda + k0 + ac);
#pragma unroll
            for (int p = 0; p < 4; p++)
                cp16(&Bs[nxt][brow + 4 * p][bc], Bg + (size_t)(k0 + brow + 4 * p) * ldb + bc);
            cp_commit();
            asm volatile("cp.async.wait_group 1;\n" ::);
        } else {
            asm volatile("cp.async.wait_group 0;\n" ::);
        }
        __syncthreads();
        compute_k8_nn(As[cur], Bs[cur], acc, 0, wm, wn, g, tig);
        compute_k8_nn(As[cur], Bs[cur], acc, 8, wm, wn, g, tig);
        __syncthreads();
        cur ^= 1;
    }

    // epilogue
#pragma unroll
    for (int mt = 0; mt < 4; mt++) {
#pragma unroll
        for (int nt = 0; nt < 8; nt++) {
            int r = row0 + wm * 64 + mt * 16 + g;
            int c = col0 + wn * 64 + nt * 8 + tig * 2;
#pragma unroll
            for (int half = 0; half < 2; half++) {
                float* p = Cm + (size_t)(r + 8 * half) * ldc + c;
                float x0 = acc[mt][nt][2*half + 0] * scale;
                float x1 = acc[mt][nt][2*half + 1] * scale;
                if (flags & F_BIAS) { x0 += bias[c]; x1 += bias[c + 1]; }
                if (flags & F_RELU) { x0 = fmaxf(x0, 0.f); x1 = fmaxf(x1, 0.f); }
                if (flags & F_ADDC) { x0 += p[0]; x1 += p[1]; }
                p[0] = x0; p[1] = x1;
            }
        }
    }
}

// ---------------------------------------------------------------------------
// tf32 GEMM NT (scores): C = scale * A[M,K] @ B[N,K]^T, causal tile skip
// ---------------------------------------------------------------------------
__global__ void __launch_bounds__(128, 3)
mma_nt_scores(const float* __restrict__ A, const float* __restrict__ Bm,
              float* __restrict__ Cm,
              int K, int lda, int ldb, int ldc,
              long sA, long sB, long sC, float scale)
{
    int bx = blockIdx.x, by = blockIdx.y;
    if (bx > by) return;

    __shared__ float As[2][128][AP];
    __shared__ float Bt[2][128][AP];

    int z = blockIdx.z;
    A  += (long)z * sA;
    Bm += (long)z * sB;
    Cm += (long)z * sC;

    int row0 = by * 128, col0 = bx * 128;

    int tid  = threadIdx.x;
    int lane = tid & 31, warp = tid >> 5;
    int wm = warp >> 1, wn = warp & 1;
    int g  = lane >> 2, tig = lane & 3;

    const float* Ag = A  + (size_t)row0 * lda;
    const float* Bg = Bm + (size_t)col0 * ldb;
    int arow = tid >> 2, ac = (tid & 3) * 4;

    float acc[4][8][4];
#pragma unroll
    for (int i = 0; i < 4; i++)
#pragma unroll
        for (int j = 0; j < 8; j++)
#pragma unroll
            for (int r = 0; r < 4; r++) acc[i][j][r] = 0.f;

    int iters = K / 16;

    {
#pragma unroll
        for (int p = 0; p < 4; p++)
            cp16(&As[0][arow + 32 * p][ac], Ag + (size_t)(arow + 32 * p) * lda + ac);
#pragma unroll
        for (int p = 0; p < 4; p++)
            cp16(&Bt[0][arow + 32 * p][ac], Bg + (size_t)(arow + 32 * p) * ldb + ac);
        cp_commit();
    }

    int cur = 0;
    for (int it = 0; it < iters; ++it) {
        bool hn = (it + 1 < iters);
        if (hn) {
            int k0 = (it + 1) * 16;
            int nxt = cur ^ 1;
#pragma unroll
            for (int p = 0; p < 4; p++)
                cp16(&As[nxt][arow + 32 * p][ac], Ag + (size_t)(arow + 32 * p) * lda + k0 + ac);
#pragma unroll
            for (int p = 0; p < 4; p++)
                cp16(&Bt[nxt][arow + 32 * p][ac], Bg + (size_t)(arow + 32 * p) * ldb + k0 + ac);
            cp_commit();
            asm volatile("cp.async.wait_group 1;\n" ::);
        } else {
            asm volatile("cp.async.wait_group 0;\n" ::);
        }
        __syncthreads();
        compute_k8_nt(As[cur], Bt[cur], acc, 0, wm, wn, g, tig);
        compute_k8_nt(As[cur], Bt[cur], acc, 8, wm, wn, g, tig);
        __syncthreads();
        cur ^= 1;
    }

#pragma unroll
    for (int mt = 0; mt < 4; mt++) {
#pragma unroll
        for (int nt = 0; nt < 8; nt++) {
            int r = row0 + wm * 64 + mt * 16 + g;
            int c = col0 + wn * 64 + nt * 8 + tig * 2;
#pragma unroll
            for (int half = 0; half < 2; half++) {
                float* p = Cm + (size_t)(r + 8 * half) * ldc + c;
                p[0] = acc[mt][nt][2*half + 0] * scale;
                p[1] = acc[mt][nt][2*half + 1] * scale;
            }
        }
    }
}

// ---------------------------------------------------------------------------
// Host launch
// ---------------------------------------------------------------------------
extern "C" void kernel_launch(void* const* d_in, const int* in_sizes, int n_in,
                              void* d_out, int out_size) {
    const int*   idx = (const int*)  d_in[0];
    const float* tok = (const float*)d_in[1];
    const float* pos = (const float*)d_in[2];
    const float* Wq  = (const float*)d_in[3];
    const float* Wk  = (const float*)d_in[4];
    const float* Wv  = (const float*)d_in[5];
    const float* Wo  = (const float*)d_in[6];
    const float* bo  = (const float*)d_in[7];
    const float* W1  = (const float*)d_in[8];
    const float* b1  = (const float*)d_in[9];
    const float* W2  = (const float*)d_in[10];
    const float* b2  = (const float*)d_in[11];
    const float* g1  = (const float*)d_in[12];
    const float* be1 = (const float*)d_in[13];
    const float* g2  = (const float*)d_in[14];
    const float* be2 = (const float*)d_in[15];
    const float* gf  = (const float*)d_in[16];
    const float* bef = (const float*)d_in[17];
    const float* Wlm = (const float*)d_in[18];
    const float* blm = (const float*)d_in[19];
    float* out = (float*)d_out;

    float *x, *h, *q, *k, *v, *att, *ffn, *wei;
    cudaGetSymbolAddress((void**)&x,   g_x);
    cudaGetSymbolAddress((void**)&h,   g_h);
    cudaGetSymbolAddress((void**)&q,   g_q);
    cudaGetSymbolAddress((void**)&k,   g_k);
    cudaGetSymbolAddress((void**)&v,   g_v);
    cudaGetSymbolAddress((void**)&att, g_att);
    cudaGetSymbolAddress((void**)&ffn, g_ffn);
    cudaGetSymbolAddress((void**)&wei, g_wei);

    // 1. embedding
    embed_kernel<<<(B_*T_*C_)/256, 256>>>(idx, tok, pos);

    // 2. LN1
    ln_kernel<<<B_*T_, 256>>>(x, h, g1, be1);

    // 3. q,k,v projections
    {
        dim3 grid(D_/128, T_/128, B_*H_);
        long sAb = (long)T_*C_, sBh = (long)C_*D_;
        long sCb = (long)H_*T_*D_, sCh = (long)T_*D_;
        mma_nn<<<grid, 128>>>(h, Wq, q, C_, C_, D_, D_,
                              sAb, 0, 0, sBh, sCb, sCh, H_, nullptr, 1.f, 0);
        mma_nn<<<grid, 128>>>(h, Wk, k, C_, C_, D_, D_,
                              sAb, 0, 0, sBh, sCb, sCh, H_, nullptr, 1.f, 0);
        mma_nn<<<grid, 128>>>(h, Wv, v, C_, C_, D_, D_,
                              sAb, 0, 0, sBh, sCb, sCh, H_, nullptr, 1.f, 0);
    }

    // 4. scores
    {
        dim3 grid(T_/128, T_/128, B_*H_);
        mma_nt_scores<<<grid, 128>>>(q, k, wei, D_, D_, D_, T_,
                                     (long)T_*D_, (long)T_*D_, (long)T_*T_,
                                     rsqrtf((float)D_));
    }

    // 5. softmax
    softmax_kernel<<<B_*H_*T_, 256>>>(wei);

    // 6. att = wei @ v  ([B,T,H*D] layout, causal K-limit)
    {
        dim3 grid(D_/128, T_/128, B_*H_);
        mma_nn<<<grid, 128>>>(wei, v, att, T_, T_, D_, HD_,
                              (long)H_*T_*T_, (long)T_*T_,
                              (long)H_*T_*D_, (long)T_*D_,
                              (long)T_*HD_, (long)D_, H_,
                              nullptr, 1.f, F_CAUSALK);
    }

    // 7. x += att @ Wo + bo
    mma_nn<<<dim3(C_/128, (B_*T_)/128, 1), 128>>>(
        att, Wo, x, HD_, HD_, C_, C_,
        0, 0, 0, 0, 0, 0, 1, bo, 1.f, F_BIAS | F_ADDC);

    // 8. LN2
    ln_kernel<<<B_*T_, 256>>>(x, h, g2, be2);

    // 9. ffn = relu(h @ W1 + b1)
    mma_nn<<<dim3(FF_/128, (B_*T_)/128, 1), 128>>>(
        h, W1, ffn, C_, C_, FF_, FF_,
        0, 0, 0, 0, 0, 0, 1, b1, 1.f, F_BIAS | F_RELU);

    // 10. x += ffn @ W2 + b2
    mma_nn<<<dim3(C_/128, (B_*T_)/128, 1), 128>>>(
        ffn, W2, x, FF_, FF_, C_, C_,
        0, 0, 0, 0, 0, 0, 1, b2, 1.f, F_BIAS | F_ADDC);

    // 11. final LN
    ln_kernel<<<B_*T_, 256>>>(x, h, gf, bef);

    // 12. logits = h @ Wlm + blm
    mma_nn<<<dim3(V_/128, (B_*T_)/128, 1), 128>>>(
        h, Wlm, out, C_, C_, V_, V_,
        0, 0, 0, 0, 0, 0, 1, blm, 1.f, F_BIAS);
}